// round 1
// baseline (speedup 1.0000x reference)
#include <cuda_runtime.h>
#include <math.h>

// Problem dims (fixed by the reference)
#define NN_ 8192
#define DD_ 512
#define HH_ 512

// Scratch (no cudaMalloc allowed — use __device__ globals)
__device__ float g_q[(size_t)NN_ * HH_];
__device__ float g_k[(size_t)NN_ * HH_];
__device__ float g_v[(size_t)NN_ * HH_];
__device__ float g_s[(size_t)NN_ * NN_];      // scores / attn (in-place softmax), 256 MB
__device__ float g_t[(size_t)NN_ * HH_];      // attended

// ----------------------------------------------------------------------------
// Classic fp32 SMEM-tiled GEMM: C = alpha * A @ B(^T) + bias
//   A: [M, K] row-major
//   B: TRANSB ? [Ncols, K] : [K, Ncols] row-major
//   C: [M, Ncols]
// BM=BN=128, BK=16, 256 threads, 8x8 per thread.
// All dims assumed multiples of tile sizes (true for this problem).
// ----------------------------------------------------------------------------
template <bool TRANSB>
__global__ void __launch_bounds__(256)
gemm_kernel(const float* __restrict__ A, const float* __restrict__ B,
            const float* __restrict__ bias, float* __restrict__ C,
            int M, int Ncols, int K, float alpha)
{
    constexpr int BM = 128, BN = 128, BK = 16;
    __shared__ float As[BK][BM + 4];
    __shared__ float Bs[BK][BN + 4];

    const int tid = threadIdx.x;
    const int tx = tid & 15;           // 0..15  -> column group
    const int ty = tid >> 4;           // 0..15  -> row group
    const int row0 = blockIdx.y * BM;
    const int col0 = blockIdx.x * BN;

    float acc[8][8];
#pragma unroll
    for (int i = 0; i < 8; i++)
#pragma unroll
        for (int j = 0; j < 8; j++) acc[i][j] = 0.0f;

    for (int k0 = 0; k0 < K; k0 += BK) {
        // ---- load A tile [BM x BK], store transposed As[k][m] ----
#pragma unroll
        for (int it = 0; it < 2; it++) {
            int li = tid + it * 256;         // 512 float4 loads
            int r  = li >> 2;                // 0..127
            int kc = li & 3;                 // 0..3
            float4 va = *reinterpret_cast<const float4*>(
                &A[(size_t)(row0 + r) * K + k0 + kc * 4]);
            As[kc * 4 + 0][r] = va.x;
            As[kc * 4 + 1][r] = va.y;
            As[kc * 4 + 2][r] = va.z;
            As[kc * 4 + 3][r] = va.w;
        }
        // ---- load B tile -> Bs[k][n] ----
        if (TRANSB) {
            // B is [Ncols, K]; need Bs[kk][j] = B[col0+j][k0+kk]
#pragma unroll
            for (int it = 0; it < 2; it++) {
                int li = tid + it * 256;
                int j  = li >> 2;
                int kc = li & 3;
                float4 vb = *reinterpret_cast<const float4*>(
                    &B[(size_t)(col0 + j) * K + k0 + kc * 4]);
                Bs[kc * 4 + 0][j] = vb.x;
                Bs[kc * 4 + 1][j] = vb.y;
                Bs[kc * 4 + 2][j] = vb.z;
                Bs[kc * 4 + 3][j] = vb.w;
            }
        } else {
            // B is [K, Ncols]
#pragma unroll
            for (int it = 0; it < 2; it++) {
                int li = tid + it * 256;
                int kk = li >> 5;            // 0..15
                int jc = li & 31;            // 0..31 (float4 granules)
                float4 vb = *reinterpret_cast<const float4*>(
                    &B[(size_t)(k0 + kk) * Ncols + col0 + jc * 4]);
                *reinterpret_cast<float4*>(&Bs[kk][jc * 4]) = vb;
            }
        }
        __syncthreads();

        // ---- compute ----
#pragma unroll
        for (int kk = 0; kk < BK; kk++) {
            float4 a0 = *reinterpret_cast<const float4*>(&As[kk][ty * 8]);
            float4 a1 = *reinterpret_cast<const float4*>(&As[kk][ty * 8 + 4]);
            float4 b0 = *reinterpret_cast<const float4*>(&Bs[kk][tx * 8]);
            float4 b1 = *reinterpret_cast<const float4*>(&Bs[kk][tx * 8 + 4]);
            float a[8] = {a0.x, a0.y, a0.z, a0.w, a1.x, a1.y, a1.z, a1.w};
            float b[8] = {b0.x, b0.y, b0.z, b0.w, b1.x, b1.y, b1.z, b1.w};
#pragma unroll
            for (int i = 0; i < 8; i++)
#pragma unroll
                for (int j = 0; j < 8; j++)
                    acc[i][j] = fmaf(a[i], b[j], acc[i][j]);
        }
        __syncthreads();
    }

    // ---- epilogue ----
    float bb[8];
#pragma unroll
    for (int j = 0; j < 8; j++)
        bb[j] = bias ? bias[col0 + tx * 8 + j] : 0.0f;

#pragma unroll
    for (int i = 0; i < 8; i++) {
        int r = row0 + ty * 8 + i;
        float4 o0, o1;
        o0.x = alpha * acc[i][0] + bb[0];
        o0.y = alpha * acc[i][1] + bb[1];
        o0.z = alpha * acc[i][2] + bb[2];
        o0.w = alpha * acc[i][3] + bb[3];
        o1.x = alpha * acc[i][4] + bb[4];
        o1.y = alpha * acc[i][5] + bb[5];
        o1.z = alpha * acc[i][6] + bb[6];
        o1.w = alpha * acc[i][7] + bb[7];
        *reinterpret_cast<float4*>(&C[(size_t)r * Ncols + col0 + tx * 8])     = o0;
        *reinterpret_cast<float4*>(&C[(size_t)r * Ncols + col0 + tx * 8 + 4]) = o1;
    }
}

// ----------------------------------------------------------------------------
// Row softmax, in place. One block per row, 256 threads, 32 f32/thread in regs.
// ----------------------------------------------------------------------------
__global__ void __launch_bounds__(256)
softmax_rows(float* __restrict__ S, int n)
{
    const int row = blockIdx.x;
    const int tid = threadIdx.x;
    float* rowp = S + (size_t)row * n;

    float v[32];
#pragma unroll
    for (int i = 0; i < 32; i++) v[i] = rowp[tid + i * 256];

    // max reduce
    float m = -INFINITY;
#pragma unroll
    for (int i = 0; i < 32; i++) m = fmaxf(m, v[i]);
#pragma unroll
    for (int o = 16; o > 0; o >>= 1)
        m = fmaxf(m, __shfl_xor_sync(0xFFFFFFFFu, m, o));
    __shared__ float red[8];
    if ((tid & 31) == 0) red[tid >> 5] = m;
    __syncthreads();
    if (tid < 32) {
        float t = (tid < 8) ? red[tid] : -INFINITY;
#pragma unroll
        for (int o = 4; o > 0; o >>= 1)
            t = fmaxf(t, __shfl_xor_sync(0xFFFFFFFFu, t, o));
        if (tid == 0) red[0] = t;
    }
    __syncthreads();
    m = red[0];

    // exp + sum reduce
    float s = 0.0f;
#pragma unroll
    for (int i = 0; i < 32; i++) {
        v[i] = __expf(v[i] - m);
        s += v[i];
    }
#pragma unroll
    for (int o = 16; o > 0; o >>= 1)
        s += __shfl_xor_sync(0xFFFFFFFFu, s, o);
    __syncthreads();
    if ((tid & 31) == 0) red[tid >> 5] = s;
    __syncthreads();
    if (tid < 32) {
        float t = (tid < 8) ? red[tid] : 0.0f;
#pragma unroll
        for (int o = 4; o > 0; o >>= 1)
            t += __shfl_xor_sync(0xFFFFFFFFu, t, o);
        if (tid == 0) red[0] = t;
    }
    __syncthreads();
    const float inv = 1.0f / red[0];

#pragma unroll
    for (int i = 0; i < 32; i++) rowp[tid + i * 256] = v[i] * inv;
}

// ----------------------------------------------------------------------------
extern "C" void kernel_launch(void* const* d_in, const int* in_sizes, int n_in,
                              void* d_out, int out_size)
{
    const float* x  = (const float*)d_in[0];
    const float* Wq = (const float*)d_in[1];
    const float* bq = (const float*)d_in[2];
    const float* Wk = (const float*)d_in[3];
    const float* bk = (const float*)d_in[4];
    const float* Wv = (const float*)d_in[5];
    const float* bv = (const float*)d_in[6];
    const float* Wo = (const float*)d_in[7];
    const float* bo = (const float*)d_in[8];
    float* out = (float*)d_out;

    float *q, *k, *v, *s, *t;
    cudaGetSymbolAddress((void**)&q, g_q);
    cudaGetSymbolAddress((void**)&k, g_k);
    cudaGetSymbolAddress((void**)&v, g_v);
    cudaGetSymbolAddress((void**)&s, g_s);
    cudaGetSymbolAddress((void**)&t, g_t);

    const float scale = 1.0f / sqrtf((float)HH_);

    dim3 blk(256);
    dim3 gProj(HH_ / 128, NN_ / 128);   // (4, 64)
    dim3 gScores(NN_ / 128, NN_ / 128); // (64, 64)

    // QKV projections
    gemm_kernel<false><<<gProj, blk>>>(x, Wq, bq, q, NN_, HH_, DD_, 1.0f);
    gemm_kernel<false><<<gProj, blk>>>(x, Wk, bk, k, NN_, HH_, DD_, 1.0f);
    gemm_kernel<false><<<gProj, blk>>>(x, Wv, bv, v, NN_, HH_, DD_, 1.0f);

    // scores = scale * q @ k^T
    gemm_kernel<true><<<gScores, blk>>>(q, k, nullptr, s, NN_, NN_, HH_, scale);

    // softmax rows (in place)
    softmax_rows<<<NN_, blk>>>(s, NN_);

    // attended = attn @ v
    gemm_kernel<false><<<gProj, blk>>>(s, v, nullptr, t, NN_, HH_, NN_, 1.0f);

    // out = attended @ Wo + bo
    gemm_kernel<false><<<gProj, blk>>>(t, Wo, bo, out, NN_, HH_, HH_, 1.0f);
}

// round 3
// speedup vs baseline: 1.5784x; 1.5784x over previous
#include <cuda_runtime.h>
#include <math.h>
#include <stdint.h>

#define NTOK 8192
#define DIM  512

// ------------------------- scratch (__device__ globals) -------------------------
__device__ float g_xc [(size_t)NTOK * DIM];
__device__ float g_wqT[(size_t)DIM * DIM];
__device__ float g_wkT[(size_t)DIM * DIM];
__device__ float g_wvT[(size_t)DIM * DIM];
__device__ float g_woT[(size_t)DIM * DIM];
__device__ float g_q  [(size_t)NTOK * DIM];
__device__ float g_k  [(size_t)NTOK * DIM];
__device__ float g_v  [(size_t)NTOK * DIM];
__device__ float g_vT [(size_t)DIM * NTOK];
__device__ float g_t  [(size_t)NTOK * DIM];
__device__ float g_s  [(size_t)NTOK * NTOK];   // 256 MB scores/attn

// ------------------------- helpers -------------------------
__device__ __forceinline__ float rna_tf32(float x) {
    uint32_t u;
    asm("cvt.rna.tf32.f32 %0, %1;" : "=r"(u) : "f"(x));
    return __uint_as_float(u);
}

// mma.sync m16n8k8 tf32 (portable sm_80+ — works on base sm_103 target)
__device__ __forceinline__ void mma_tf32(float* d, const uint32_t* a,
                                         const uint32_t* b) {
    asm volatile(
        "mma.sync.aligned.m16n8k8.row.col.f32.tf32.tf32.f32 "
        "{%0,%1,%2,%3}, {%4,%5,%6,%7}, {%8,%9}, {%0,%1,%2,%3};"
        : "+f"(d[0]), "+f"(d[1]), "+f"(d[2]), "+f"(d[3])
        : "r"(a[0]), "r"(a[1]), "r"(a[2]), "r"(a[3]),
          "r"(b[0]), "r"(b[1]));
}

// ------------------------- tf32 tensor-core GEMM -------------------------
// C[M,N] = alpha * (A @ Bt^T) + bias,  A:[M,K], Bt:[N,K] row-major.
// Tile 128x128xBK32, 256 threads (8 warps, 2x4), warp tile 64x32.
// Dims are multiples of 128/32 (true for this problem).

#define BK 32
#define LROW 136                 // 128 + 8 pad (conflict-free fragment LDS)
#define STAGE_FLOATS (BK * LROW)            // 4352
#define SMEM_FLOATS  (4 * STAGE_FLOATS)     // A0,B0,A1,B1
#define SMEM_BYTES   (SMEM_FLOATS * 4)      // 69632

template <bool ROUND_OUT>
__global__ void __launch_bounds__(256, 1)
mma_gemm(const float* __restrict__ A, const float* __restrict__ Bt,
         const float* __restrict__ bias, float* __restrict__ C,
         int M, int N, int K, float alpha)
{
    extern __shared__ float smf[];
    const int tid = threadIdx.x;
    const int wid = tid >> 5;
    const int lid = tid & 31;
    const int grp = lid >> 2;         // 0..7
    const int tig = lid & 3;          // 0..3
    const int wm  = wid >> 2;         // 0..1  -> warp row (64 rows)
    const int wn  = wid & 3;          // 0..3  -> warp col (32 cols)
    const int m0  = wm * 64;
    const int n0  = wn * 32;
    const int row0 = blockIdx.y * 128;
    const int col0 = blockIdx.x * 128;
    const int KT = K >> 5;

    // global load coords: 4 float4 each for A and B per stage
    const int lr = tid >> 3;          // 0..31 (base row, step 32)
    const int lc = tid & 7;           // 0..7  (float4 within 32-k row)

    float acc[4][4][4];
#pragma unroll
    for (int i = 0; i < 4; i++)
#pragma unroll
        for (int j = 0; j < 4; j++)
#pragma unroll
            for (int e = 0; e < 4; e++) acc[i][j][e] = 0.0f;

    float4 ra[4], rb[4];
    // preload tile 0
#pragma unroll
    for (int i = 0; i < 4; i++) {
        int r = lr + i * 32;
        ra[i] = *reinterpret_cast<const float4*>(A  + (size_t)(row0 + r) * K + lc * 4);
        rb[i] = *reinterpret_cast<const float4*>(Bt + (size_t)(col0 + r) * K + lc * 4);
    }

    int buf = 0;
    for (int kt = 0; kt < KT; kt++) {
        float* As = smf + buf * 2 * STAGE_FLOATS;
        float* Bs = As + STAGE_FLOATS;

        // store stage (transpose in-flight: smem is [k][m] / [k][n])
#pragma unroll
        for (int i = 0; i < 4; i++) {
            int r = lr + i * 32;
            As[(lc * 4 + 0) * LROW + r] = ra[i].x;
            As[(lc * 4 + 1) * LROW + r] = ra[i].y;
            As[(lc * 4 + 2) * LROW + r] = ra[i].z;
            As[(lc * 4 + 3) * LROW + r] = ra[i].w;
            Bs[(lc * 4 + 0) * LROW + r] = rb[i].x;
            Bs[(lc * 4 + 1) * LROW + r] = rb[i].y;
            Bs[(lc * 4 + 2) * LROW + r] = rb[i].z;
            Bs[(lc * 4 + 3) * LROW + r] = rb[i].w;
        }
        __syncthreads();

        // prefetch next tile into regs (overlaps with compute)
        if (kt + 1 < KT) {
            int k0 = (kt + 1) * BK;
#pragma unroll
            for (int i = 0; i < 4; i++) {
                int r = lr + i * 32;
                ra[i] = *reinterpret_cast<const float4*>(A  + (size_t)(row0 + r) * K + k0 + lc * 4);
                rb[i] = *reinterpret_cast<const float4*>(Bt + (size_t)(col0 + r) * K + k0 + lc * 4);
            }
        }

        // compute: 4 k-steps of 8
#pragma unroll
        for (int kk = 0; kk < 4; kk++) {
            const float* Ak0 = As + (kk * 8 + tig) * LROW;
            const float* Ak4 = As + (kk * 8 + tig + 4) * LROW;
            const float* Bk0 = Bs + (kk * 8 + tig) * LROW;
            const float* Bk4 = Bs + (kk * 8 + tig + 4) * LROW;

            uint32_t af[4][4];
#pragma unroll
            for (int i = 0; i < 4; i++) {
                int mr = m0 + i * 16 + grp;
                af[i][0] = __float_as_uint(Ak0[mr]);
                af[i][1] = __float_as_uint(Ak0[mr + 8]);
                af[i][2] = __float_as_uint(Ak4[mr]);
                af[i][3] = __float_as_uint(Ak4[mr + 8]);
            }
            uint32_t bf[4][2];
#pragma unroll
            for (int j = 0; j < 4; j++) {
                int nc = n0 + j * 8 + grp;
                bf[j][0] = __float_as_uint(Bk0[nc]);
                bf[j][1] = __float_as_uint(Bk4[nc]);
            }
#pragma unroll
            for (int i = 0; i < 4; i++)
#pragma unroll
                for (int j = 0; j < 4; j++)
                    mma_tf32(acc[i][j], af[i], bf[j]);
        }
        __syncthreads();   // stage fully consumed before it is overwritten
        buf ^= 1;
    }

    // ---- epilogue ----
#pragma unroll
    for (int j = 0; j < 4; j++) {
        int col = col0 + n0 + j * 8 + tig * 2;
        float b0 = bias ? bias[col]     : 0.0f;
        float b1 = bias ? bias[col + 1] : 0.0f;
#pragma unroll
        for (int i = 0; i < 4; i++) {
            int rowA = row0 + m0 + i * 16 + grp;
            float f0 = alpha * acc[i][j][0] + b0;
            float f1 = alpha * acc[i][j][1] + b1;
            float f2 = alpha * acc[i][j][2] + b0;
            float f3 = alpha * acc[i][j][3] + b1;
            if (ROUND_OUT) {
                f0 = rna_tf32(f0); f1 = rna_tf32(f1);
                f2 = rna_tf32(f2); f3 = rna_tf32(f3);
            }
            *reinterpret_cast<float2*>(C + (size_t)rowA * N + col) = make_float2(f0, f1);
            *reinterpret_cast<float2*>(C + (size_t)(rowA + 8) * N + col) = make_float2(f2, f3);
        }
    }
}

// ------------------------- elementwise rna convert -------------------------
__global__ void __launch_bounds__(256)
convert_rna(const float* __restrict__ src, float* __restrict__ dst, int n4)
{
    int i = blockIdx.x * blockDim.x + threadIdx.x;
    if (i < n4) {
        float4 v = reinterpret_cast<const float4*>(src)[i];
        v.x = rna_tf32(v.x); v.y = rna_tf32(v.y);
        v.z = rna_tf32(v.z); v.w = rna_tf32(v.w);
        reinterpret_cast<float4*>(dst)[i] = v;
    }
}

// ------------------------- transpose + rna -------------------------
__global__ void __launch_bounds__(256)
transpose_rna(const float* __restrict__ src, float* __restrict__ dst, int R, int C)
{
    __shared__ float t[32][33];
    int c = blockIdx.x * 32 + threadIdx.x;
    int r = blockIdx.y * 32 + threadIdx.y;
#pragma unroll
    for (int i = 0; i < 32; i += 8)
        t[threadIdx.y + i][threadIdx.x] = src[(size_t)(r + i) * C + c];
    __syncthreads();
    int c2 = blockIdx.y * 32 + threadIdx.x;
    int r2 = blockIdx.x * 32 + threadIdx.y;
#pragma unroll
    for (int i = 0; i < 32; i += 8)
        dst[(size_t)(r2 + i) * R + c2] = rna_tf32(t[threadIdx.x][threadIdx.y + i]);
}

// ------------------------- row softmax (in place) + rna -------------------------
__global__ void __launch_bounds__(256)
softmax_rows(float* __restrict__ S, int n)
{
    const int row = blockIdx.x;
    const int tid = threadIdx.x;
    float* rowp = S + (size_t)row * n;

    float v[32];
#pragma unroll
    for (int i = 0; i < 32; i++) v[i] = rowp[tid + i * 256];

    float m = -INFINITY;
#pragma unroll
    for (int i = 0; i < 32; i++) m = fmaxf(m, v[i]);
#pragma unroll
    for (int o = 16; o > 0; o >>= 1) m = fmaxf(m, __shfl_xor_sync(0xFFFFFFFFu, m, o));
    __shared__ float red[8];
    if ((tid & 31) == 0) red[tid >> 5] = m;
    __syncthreads();
    if (tid < 32) {
        float t = (tid < 8) ? red[tid] : -INFINITY;
#pragma unroll
        for (int o = 4; o > 0; o >>= 1) t = fmaxf(t, __shfl_xor_sync(0xFFFFFFFFu, t, o));
        if (tid == 0) red[0] = t;
    }
    __syncthreads();
    m = red[0];

    float s = 0.0f;
#pragma unroll
    for (int i = 0; i < 32; i++) { v[i] = __expf(v[i] - m); s += v[i]; }
#pragma unroll
    for (int o = 16; o > 0; o >>= 1) s += __shfl_xor_sync(0xFFFFFFFFu, s, o);
    __syncthreads();
    if ((tid & 31) == 0) red[tid >> 5] = s;
    __syncthreads();
    if (tid < 32) {
        float t = (tid < 8) ? red[tid] : 0.0f;
#pragma unroll
        for (int o = 4; o > 0; o >>= 1) t += __shfl_xor_sync(0xFFFFFFFFu, t, o);
        if (tid == 0) red[0] = t;
    }
    __syncthreads();
    const float inv = 1.0f / red[0];

#pragma unroll
    for (int i = 0; i < 32; i++) rowp[tid + i * 256] = rna_tf32(v[i] * inv);
}

// ------------------------- launch -------------------------
extern "C" void kernel_launch(void* const* d_in, const int* in_sizes, int n_in,
                              void* d_out, int out_size)
{
    const float* x  = (const float*)d_in[0];
    const float* Wq = (const float*)d_in[1];
    const float* bq = (const float*)d_in[2];
    const float* Wk = (const float*)d_in[3];
    const float* bk = (const float*)d_in[4];
    const float* Wv = (const float*)d_in[5];
    const float* bv = (const float*)d_in[6];
    const float* Wo = (const float*)d_in[7];
    const float* bo = (const float*)d_in[8];
    float* out = (float*)d_out;

    float *xc, *wqT, *wkT, *wvT, *woT, *q, *k, *v, *vT, *t, *s;
    cudaGetSymbolAddress((void**)&xc,  g_xc);
    cudaGetSymbolAddress((void**)&wqT, g_wqT);
    cudaGetSymbolAddress((void**)&wkT, g_wkT);
    cudaGetSymbolAddress((void**)&wvT, g_wvT);
    cudaGetSymbolAddress((void**)&woT, g_woT);
    cudaGetSymbolAddress((void**)&q,   g_q);
    cudaGetSymbolAddress((void**)&k,   g_k);
    cudaGetSymbolAddress((void**)&v,   g_v);
    cudaGetSymbolAddress((void**)&vT,  g_vT);
    cudaGetSymbolAddress((void**)&t,   g_t);
    cudaGetSymbolAddress((void**)&s,   g_s);

    cudaFuncSetAttribute(mma_gemm<true>,  cudaFuncAttributeMaxDynamicSharedMemorySize, SMEM_BYTES);
    cudaFuncSetAttribute(mma_gemm<false>, cudaFuncAttributeMaxDynamicSharedMemorySize, SMEM_BYTES);

    const float scale = 1.0f / sqrtf((float)DIM);
    dim3 blk(256);

    // tf32-round inputs (rna, unbiased); transpose weights to [N,K]
    convert_rna<<<(NTOK * DIM / 4 + 255) / 256, blk>>>(x, xc, NTOK * DIM / 4);
    {
        dim3 tb(32, 8), tg(DIM / 32, DIM / 32);
        transpose_rna<<<tg, tb>>>(Wq, wqT, DIM, DIM);
        transpose_rna<<<tg, tb>>>(Wk, wkT, DIM, DIM);
        transpose_rna<<<tg, tb>>>(Wv, wvT, DIM, DIM);
        transpose_rna<<<tg, tb>>>(Wo, woT, DIM, DIM);
    }

    dim3 gProj(DIM / 128, NTOK / 128);     // (4, 64)
    dim3 gScores(NTOK / 128, NTOK / 128);  // (64, 64)

    // projections (outputs tf32-rounded: they feed later MMAs)
    mma_gemm<true><<<gProj, blk, SMEM_BYTES>>>(xc, wqT, bq, q, NTOK, DIM, DIM, 1.0f);
    mma_gemm<true><<<gProj, blk, SMEM_BYTES>>>(xc, wkT, bk, k, NTOK, DIM, DIM, 1.0f);
    mma_gemm<true><<<gProj, blk, SMEM_BYTES>>>(xc, wvT, bv, v, NTOK, DIM, DIM, 1.0f);

    // v^T for the attn@v GEMM (K-major B operand)
    {
        dim3 tb(32, 8), tg(DIM / 32, NTOK / 32);
        transpose_rna<<<tg, tb>>>(v, vT, NTOK, DIM);
    }

    // scores = scale * q @ k^T
    mma_gemm<false><<<gScores, blk, SMEM_BYTES>>>(q, k, nullptr, s, NTOK, NTOK, DIM, scale);

    // softmax rows in place (writes tf32-rounded attn)
    softmax_rows<<<NTOK, blk>>>(s, NTOK);

    // attended = attn @ v  (= attn @ vT^T)
    mma_gemm<true><<<gProj, blk, SMEM_BYTES>>>(s, vT, nullptr, t, NTOK, DIM, NTOK, 1.0f);

    // out = attended @ Wo + bo
    mma_gemm<false><<<gProj, blk, SMEM_BYTES>>>(t, woT, bo, out, NTOK, DIM, DIM, 1.0f);
}

// round 5
// speedup vs baseline: 7.2042x; 4.5643x over previous
#include <cuda_runtime.h>
#include <cuda_fp16.h>
#include <math.h>
#include <stdint.h>

#define NTOK 8192
#define DIM  512

// ------------------------- scratch (__device__ globals, 16B-alignable) -------------------------
__device__ __align__(256) __half g_xh [(size_t)NTOK * DIM];
__device__ __align__(256) __half g_wqT[(size_t)DIM * DIM];
__device__ __align__(256) __half g_wkT[(size_t)DIM * DIM];
__device__ __align__(256) __half g_wvT[(size_t)DIM * DIM];
__device__ __align__(256) __half g_woT[(size_t)DIM * DIM];
__device__ __align__(256) __half g_q  [(size_t)NTOK * DIM];
__device__ __align__(256) __half g_k  [(size_t)NTOK * DIM];
__device__ __align__(256) __half g_v  [(size_t)NTOK * DIM];
__device__ __align__(256) __half g_vT [(size_t)DIM * NTOK];
__device__ __align__(256) __half g_t  [(size_t)NTOK * DIM];
__device__ __align__(256) __half g_s  [(size_t)NTOK * NTOK];   // 128 MB scores/attn

// ------------------------- helpers -------------------------
__device__ __forceinline__ uint32_t smem_u32(const void* p) {
    uint32_t a;
    asm("{ .reg .u64 t; cvta.to.shared.u64 t, %1; cvt.u32.u64 %0, t; }" : "=r"(a) : "l"(p));
    return a;
}

__device__ __forceinline__ void mma_f16(float* d, const uint32_t* a, const uint32_t* b) {
    asm volatile(
        "mma.sync.aligned.m16n8k16.row.col.f32.f16.f16.f32 "
        "{%0,%1,%2,%3}, {%4,%5,%6,%7}, {%8,%9}, {%0,%1,%2,%3};"
        : "+f"(d[0]), "+f"(d[1]), "+f"(d[2]), "+f"(d[3])
        : "r"(a[0]), "r"(a[1]), "r"(a[2]), "r"(a[3]),
          "r"(b[0]), "r"(b[1]));
}

__device__ __forceinline__ void cph16(uint32_t dst, const __half* src) {
    asm volatile("cp.async.cg.shared.global [%0], [%1], 16;\n" :: "r"(dst), "l"(src));
}

__device__ __forceinline__ void store2(__half* C, size_t off, float a, float b) {
    *reinterpret_cast<__half2*>(C + off) = __floats2half2_rn(a, b);
}
__device__ __forceinline__ void store2(float* C, size_t off, float a, float b) {
    *reinterpret_cast<float2*>(C + off) = make_float2(a, b);
}

// ------------------------- fp16 tensor-core GEMM -------------------------
// C[M,N] = alpha * (A @ Bt^T) + bias.  A:[M,K] half, Bt:[N,K] half (both K-major).
// Tile 128x128, k-chunk 64 halves (128B rows, XOR-swizzled), 256 threads,
// 8 warps 2x4 (warp tile 64x32), cp.async double buffer, ldmatrix fragments.
// All dims multiples of 128/64 (true for this problem).

#define BM 128
#define BN 128
#define STAGE_BYTES (BM * 128 + BN * 128)     // 32768
#define SMEM_BYTES  (2 * STAGE_BYTES + 128)

__device__ __forceinline__ void load_stage_h(const __half* __restrict__ Ag,
                                             const __half* __restrict__ Bg,
                                             int K, uint32_t Ab, uint32_t Bb, int tid)
{
    // Ag/Bg point at (row0, k0) / (col0, k0). 8 chunks of 16B per 128B row.
#pragma unroll
    for (int i = 0; i < 4; i++) {
        int c = tid + i * 256;           // 0..1023
        int m = c >> 3, ko = c & 7;
        cph16(Ab + m * 128 + ((ko ^ (m & 7)) << 4), Ag + (size_t)m * K + ko * 8);
    }
#pragma unroll
    for (int i = 0; i < 4; i++) {
        int c = tid + i * 256;
        int m = c >> 3, ko = c & 7;
        cph16(Bb + m * 128 + ((ko ^ (m & 7)) << 4), Bg + (size_t)m * K + ko * 8);
    }
    asm volatile("cp.async.commit_group;" ::: "memory");
}

template <typename OutT>
__global__ void __launch_bounds__(256, 2)
hgemm(const __half* __restrict__ A, const __half* __restrict__ Bt,
      const float* __restrict__ bias, OutT* __restrict__ C,
      int M, int N, int K, float alpha)
{
    extern __shared__ char smraw[];
    uint32_t sb = smem_u32(smraw);
    sb = (sb + 127u) & ~127u;               // 128B-align for swizzle

    const int tid = threadIdx.x;
    const int lid = tid & 31;
    const int wid = tid >> 5;
    const int grp = lid >> 2;               // 0..7
    const int tig = lid & 3;                // 0..3
    const int m0  = (wid >> 2) * 64;        // warp row (2 warps)
    const int n0  = (wid & 3) * 32;         // warp col (4 warps)
    const int row0 = blockIdx.y * BM;
    const int col0 = blockIdx.x * BN;
    const int KT = K >> 6;

    // ldmatrix lane addressing
    const int rrA  = (lid & 7) + ((lid >> 3) & 1) * 8;   // row within 16-row tile
    const int selA = (lid >> 4) & 1;                     // 16B chunk select
    const int rnB  = lid & 7;
    const int selB = (lid >> 3) & 1;

    float acc[4][4][4];
#pragma unroll
    for (int i = 0; i < 4; i++)
#pragma unroll
        for (int j = 0; j < 4; j++)
#pragma unroll
            for (int e = 0; e < 4; e++) acc[i][j][e] = 0.0f;

    const __half* Arow = A  + (size_t)row0 * K;
    const __half* Brow = Bt + (size_t)col0 * K;

    // prologue
    load_stage_h(Arow, Brow, K, sb, sb + BM * 128, tid);

    int buf = 0;
    for (int kt = 0; kt < KT; kt++) {
        if (kt + 1 < KT) {
            uint32_t Ab2 = sb + (buf ^ 1) * STAGE_BYTES;
            load_stage_h(Arow + (kt + 1) * 64, Brow + (kt + 1) * 64, K, Ab2, Ab2 + BM * 128, tid);
            asm volatile("cp.async.wait_group 1;" ::: "memory");
        } else {
            asm volatile("cp.async.wait_group 0;" ::: "memory");
        }
        __syncthreads();

        const uint32_t Ab = sb + buf * STAGE_BYTES;
        const uint32_t Bb = Ab + BM * 128;

#pragma unroll
        for (int kk = 0; kk < 4; kk++) {
            uint32_t af[4][4];
#pragma unroll
            for (int i = 0; i < 4; i++) {
                int m = m0 + i * 16 + rrA;
                uint32_t adr = Ab + m * 128 + (((kk * 2 + selA) ^ (m & 7)) << 4);
                asm volatile("ldmatrix.sync.aligned.m8n8.x4.shared.b16 {%0,%1,%2,%3}, [%4];"
                    : "=r"(af[i][0]), "=r"(af[i][1]), "=r"(af[i][2]), "=r"(af[i][3])
                    : "r"(adr));
            }
            uint32_t bf[4][2];
#pragma unroll
            for (int j = 0; j < 4; j++) {
                int n = n0 + j * 8 + rnB;
                uint32_t adr = Bb + n * 128 + (((kk * 2 + selB) ^ (n & 7)) << 4);
                asm volatile("ldmatrix.sync.aligned.m8n8.x2.shared.b16 {%0,%1}, [%2];"
                    : "=r"(bf[j][0]), "=r"(bf[j][1])
                    : "r"(adr));
            }
#pragma unroll
            for (int i = 0; i < 4; i++)
#pragma unroll
                for (int j = 0; j < 4; j++)
                    mma_f16(acc[i][j], af[i], bf[j]);
        }
        __syncthreads();     // stage consumed before overwrite next iter
        buf ^= 1;
    }

    // ---- epilogue ----
#pragma unroll
    for (int j = 0; j < 4; j++) {
        int col = col0 + n0 + j * 8 + tig * 2;
        float b0 = 0.0f, b1 = 0.0f;
        if (bias) { b0 = bias[col]; b1 = bias[col + 1]; }
#pragma unroll
        for (int i = 0; i < 4; i++) {
            int r = row0 + m0 + i * 16 + grp;
            float f0 = alpha * acc[i][j][0] + b0;
            float f1 = alpha * acc[i][j][1] + b1;
            float f2 = alpha * acc[i][j][2] + b0;
            float f3 = alpha * acc[i][j][3] + b1;
            store2(C, (size_t)r * N + col, f0, f1);
            store2(C, (size_t)(r + 8) * N + col, f2, f3);
        }
    }
}

// ------------------------- conversion / transpose kernels -------------------------
__global__ void __launch_bounds__(256)
f2h(const float* __restrict__ src, __half* __restrict__ dst, int n4)
{
    int i = blockIdx.x * blockDim.x + threadIdx.x;
    if (i < n4) {
        float4 v = reinterpret_cast<const float4*>(src)[i];
        __half2* d2 = reinterpret_cast<__half2*>(dst) + (size_t)i * 2;
        d2[0] = __floats2half2_rn(v.x, v.y);
        d2[1] = __floats2half2_rn(v.z, v.w);
    }
}

__global__ void __launch_bounds__(256)
transpose_f2h(const float* __restrict__ src, __half* __restrict__ dst, int R, int C)
{
    __shared__ float t[32][33];
    int c = blockIdx.x * 32 + threadIdx.x;
    int r = blockIdx.y * 32 + threadIdx.y;
#pragma unroll
    for (int i = 0; i < 32; i += 8)
        t[threadIdx.y + i][threadIdx.x] = src[(size_t)(r + i) * C + c];
    __syncthreads();
    int c2 = blockIdx.y * 32 + threadIdx.x;
    int r2 = blockIdx.x * 32 + threadIdx.y;
#pragma unroll
    for (int i = 0; i < 32; i += 8)
        dst[(size_t)(r2 + i) * R + c2] = __float2half_rn(t[threadIdx.x][threadIdx.y + i]);
}

__global__ void __launch_bounds__(256)
transpose_h(const __half* __restrict__ src, __half* __restrict__ dst, int R, int C)
{
    __shared__ __half t[32][33];
    int c = blockIdx.x * 32 + threadIdx.x;
    int r = blockIdx.y * 32 + threadIdx.y;
#pragma unroll
    for (int i = 0; i < 32; i += 8)
        t[threadIdx.y + i][threadIdx.x] = src[(size_t)(r + i) * C + c];
    __syncthreads();
    int c2 = blockIdx.y * 32 + threadIdx.x;
    int r2 = blockIdx.x * 32 + threadIdx.y;
#pragma unroll
    for (int i = 0; i < 32; i += 8)
        dst[(size_t)(r2 + i) * R + c2] = t[threadIdx.x][threadIdx.y + i];
}

// ------------------------- row softmax (half in/out, fp32 math) -------------------------
__global__ void __launch_bounds__(256)
softmax_h(__half* __restrict__ S, int n)
{
    const int row = blockIdx.x;
    const int tid = threadIdx.x;
    __half2* rp = reinterpret_cast<__half2*>(S + (size_t)row * n);

    float2 v[16];
#pragma unroll
    for (int i = 0; i < 16; i++) v[i] = __half22float2(rp[tid + i * 256]);

    float m = -INFINITY;
#pragma unroll
    for (int i = 0; i < 16; i++) m = fmaxf(m, fmaxf(v[i].x, v[i].y));
#pragma unroll
    for (int o = 16; o > 0; o >>= 1) m = fmaxf(m, __shfl_xor_sync(0xFFFFFFFFu, m, o));
    __shared__ float red[8];
    if ((tid & 31) == 0) red[tid >> 5] = m;
    __syncthreads();
    if (tid < 32) {
        float t = (tid < 8) ? red[tid] : -INFINITY;
#pragma unroll
        for (int o = 4; o > 0; o >>= 1) t = fmaxf(t, __shfl_xor_sync(0xFFFFFFFFu, t, o));
        if (tid == 0) red[0] = t;
    }
    __syncthreads();
    m = red[0];

    float s = 0.0f;
#pragma unroll
    for (int i = 0; i < 16; i++) {
        v[i].x = __expf(v[i].x - m);
        v[i].y = __expf(v[i].y - m);
        s += v[i].x + v[i].y;
    }
#pragma unroll
    for (int o = 16; o > 0; o >>= 1) s += __shfl_xor_sync(0xFFFFFFFFu, s, o);
    __syncthreads();
    if ((tid & 31) == 0) red[tid >> 5] = s;
    __syncthreads();
    if (tid < 32) {
        float t = (tid < 8) ? red[tid] : 0.0f;
#pragma unroll
        for (int o = 4; o > 0; o >>= 1) t += __shfl_xor_sync(0xFFFFFFFFu, t, o);
        if (tid == 0) red[0] = t;
    }
    __syncthreads();
    const float inv = 1.0f / red[0];

#pragma unroll
    for (int i = 0; i < 16; i++)
        rp[tid + i * 256] = __floats2half2_rn(v[i].x * inv, v[i].y * inv);
}

// ------------------------- launch -------------------------
extern "C" void kernel_launch(void* const* d_in, const int* in_sizes, int n_in,
                              void* d_out, int out_size)
{
    const float* x  = (const float*)d_in[0];
    const float* Wq = (const float*)d_in[1];
    const float* bq = (const float*)d_in[2];
    const float* Wk = (const float*)d_in[3];
    const float* bk = (const float*)d_in[4];
    const float* Wv = (const float*)d_in[5];
    const float* bv = (const float*)d_in[6];
    const float* Wo = (const float*)d_in[7];
    const float* bo = (const float*)d_in[8];
    float* out = (float*)d_out;

    __half *xh, *wqT, *wkT, *wvT, *woT, *q, *k, *v, *vT, *t, *s;
    cudaGetSymbolAddress((void**)&xh,  g_xh);
    cudaGetSymbolAddress((void**)&wqT, g_wqT);
    cudaGetSymbolAddress((void**)&wkT, g_wkT);
    cudaGetSymbolAddress((void**)&wvT, g_wvT);
    cudaGetSymbolAddress((void**)&woT, g_woT);
    cudaGetSymbolAddress((void**)&q,   g_q);
    cudaGetSymbolAddress((void**)&k,   g_k);
    cudaGetSymbolAddress((void**)&v,   g_v);
    cudaGetSymbolAddress((void**)&vT,  g_vT);
    cudaGetSymbolAddress((void**)&t,   g_t);
    cudaGetSymbolAddress((void**)&s,   g_s);

    cudaFuncSetAttribute(hgemm<__half>, cudaFuncAttributeMaxDynamicSharedMemorySize, SMEM_BYTES);
    cudaFuncSetAttribute(hgemm<float>,  cudaFuncAttributeMaxDynamicSharedMemorySize, SMEM_BYTES);

    const float scale = 1.0f / sqrtf((float)DIM);
    dim3 blk(256);

    // inputs -> half; weights -> transposed half [N][K]
    f2h<<<(NTOK * DIM / 4 + 255) / 256, blk>>>(x, xh, NTOK * DIM / 4);
    {
        dim3 tb(32, 8), tg(DIM / 32, DIM / 32);
        transpose_f2h<<<tg, tb>>>(Wq, wqT, DIM, DIM);
        transpose_f2h<<<tg, tb>>>(Wk, wkT, DIM, DIM);
        transpose_f2h<<<tg, tb>>>(Wv, wvT, DIM, DIM);
        transpose_f2h<<<tg, tb>>>(Wo, woT, DIM, DIM);
    }

    dim3 gProj(DIM / 128, NTOK / 128);     // (4, 64)
    dim3 gScores(NTOK / 128, NTOK / 128);  // (64, 64)

    // projections -> half q,k,v (half store IS the operand rounding)
    hgemm<__half><<<gProj, blk, SMEM_BYTES>>>(xh, wqT, bq, q, NTOK, DIM, DIM, 1.0f);
    hgemm<__half><<<gProj, blk, SMEM_BYTES>>>(xh, wkT, bk, k, NTOK, DIM, DIM, 1.0f);
    hgemm<__half><<<gProj, blk, SMEM_BYTES>>>(xh, wvT, bv, v, NTOK, DIM, DIM, 1.0f);

    // v^T for the attn@v GEMM
    {
        dim3 tb(32, 8), tg(DIM / 32, NTOK / 32);
        transpose_h<<<tg, tb>>>(v, vT, NTOK, DIM);
    }

    // scores = scale * q @ k^T  (half out, 128 MB)
    hgemm<__half><<<gScores, blk, SMEM_BYTES>>>(q, k, nullptr, s, NTOK, NTOK, DIM, scale);

    // softmax rows in place
    softmax_h<<<NTOK, blk>>>(s, NTOK);

    // attended = attn @ v  (= attn @ vT^T)
    hgemm<__half><<<gProj, blk, SMEM_BYTES>>>(s, vT, nullptr, t, NTOK, DIM, NTOK, 1.0f);

    // out = attended @ Wo + bo  (float out)
    hgemm<float><<<gProj, blk, SMEM_BYTES>>>(t, woT, bo, out, NTOK, DIM, DIM, 1.0f);
}

// round 6
// speedup vs baseline: 7.5245x; 1.0445x over previous
#include <cuda_runtime.h>
#include <cuda_fp16.h>
#include <math.h>
#include <stdint.h>

#define NTOK 8192
#define DIM  512

// ------------------------- scratch (__device__ globals) -------------------------
__device__ __align__(256) __half g_xh [(size_t)NTOK * DIM];
__device__ __align__(256) __half g_wqT[(size_t)DIM * DIM];
__device__ __align__(256) __half g_wkT[(size_t)DIM * DIM];
__device__ __align__(256) __half g_wvT[(size_t)DIM * DIM];
__device__ __align__(256) __half g_woT[(size_t)DIM * DIM];
__device__ __align__(256) __half g_q  [(size_t)NTOK * DIM];
__device__ __align__(256) __half g_k  [(size_t)NTOK * DIM];
__device__ __align__(256) __half g_vT [(size_t)DIM * NTOK];
__device__ __align__(256) __half g_t  [(size_t)NTOK * DIM];
__device__ __align__(256) __half g_s  [(size_t)NTOK * NTOK];   // 128 MB scores/attn

// ------------------------- helpers -------------------------
__device__ __forceinline__ uint32_t smem_u32(const void* p) {
    uint32_t a;
    asm("{ .reg .u64 t; cvta.to.shared.u64 t, %1; cvt.u32.u64 %0, t; }" : "=r"(a) : "l"(p));
    return a;
}

__device__ __forceinline__ void mma_f16(float* d, const uint32_t* a, const uint32_t* b) {
    asm volatile(
        "mma.sync.aligned.m16n8k16.row.col.f32.f16.f16.f32 "
        "{%0,%1,%2,%3}, {%4,%5,%6,%7}, {%8,%9}, {%0,%1,%2,%3};"
        : "+f"(d[0]), "+f"(d[1]), "+f"(d[2]), "+f"(d[3])
        : "r"(a[0]), "r"(a[1]), "r"(a[2]), "r"(a[3]),
          "r"(b[0]), "r"(b[1]));
}

__device__ __forceinline__ void cph16(uint32_t dst, const __half* src) {
    asm volatile("cp.async.cg.shared.global [%0], [%1], 16;\n" :: "r"(dst), "l"(src));
}

__device__ __forceinline__ void store2(__half* C, size_t off, float a, float b) {
    *reinterpret_cast<__half2*>(C + off) = __floats2half2_rn(a, b);
}
__device__ __forceinline__ void store2(float* C, size_t off, float a, float b) {
    *reinterpret_cast<float2*>(C + off) = make_float2(a, b);
}

// ------------------------- fp16 tensor-core GEMM core -------------------------
// C[M,N] = alpha * (A @ Bt^T) + bias.  A:[M,K] half, Bt:[N,K] half (both K-major).
// Tile 128x128, k-chunk 64 halves (128B swizzled rows), 256 threads, 8 warps 2x4,
// 3-stage cp.async pipeline, ldmatrix fragments.
// Dims multiples of 128/64. bias: per-col (rowbias=false) or per-row (rowbias=true).

#define BM 128
#define BN 128
#define STAGE_BYTES (BM * 128 + BN * 128)     // 32768
#define NSTAGE 3
#define SMEM_BYTES  (NSTAGE * STAGE_BYTES + 128)

__device__ __forceinline__ void load_stage_h(const __half* __restrict__ Ag,
                                             const __half* __restrict__ Bg,
                                             int K, uint32_t Ab, uint32_t Bb, int tid)
{
#pragma unroll
    for (int i = 0; i < 4; i++) {
        int c = tid + i * 256;           // 0..1023
        int m = c >> 3, ko = c & 7;
        cph16(Ab + m * 128 + ((ko ^ (m & 7)) << 4), Ag + (size_t)m * K + ko * 8);
    }
#pragma unroll
    for (int i = 0; i < 4; i++) {
        int c = tid + i * 256;
        int m = c >> 3, ko = c & 7;
        cph16(Bb + m * 128 + ((ko ^ (m & 7)) << 4), Bg + (size_t)m * K + ko * 8);
    }
    asm volatile("cp.async.commit_group;" ::: "memory");
}

template <typename OutT>
__device__ __forceinline__ void hgemm_core(
    const __half* __restrict__ A, const __half* __restrict__ Bt,
    const float* __restrict__ bias, OutT* __restrict__ C,
    int M, int N, int K, float alpha, bool rowbias,
    int bx, int by, uint32_t sb, int tid)
{
    const int lid = tid & 31;
    const int wid = tid >> 5;
    const int grp = lid >> 2;
    const int tig = lid & 3;
    const int m0  = (wid >> 2) * 64;
    const int n0  = (wid & 3) * 32;
    const int row0 = by * BM;
    const int col0 = bx * BN;
    const int KT = K >> 6;

    const int rrA  = (lid & 7) + ((lid >> 3) & 1) * 8;
    const int selA = (lid >> 4) & 1;
    const int rnB  = lid & 7;
    const int selB = (lid >> 3) & 1;

    float acc[4][4][4];
#pragma unroll
    for (int i = 0; i < 4; i++)
#pragma unroll
        for (int j = 0; j < 4; j++)
#pragma unroll
            for (int e = 0; e < 4; e++) acc[i][j][e] = 0.0f;

    const __half* Arow = A  + (size_t)row0 * K;
    const __half* Brow = Bt + (size_t)col0 * K;

    // prologue: stages 0, 1 in flight
    load_stage_h(Arow, Brow, K, sb, sb + BM * 128, tid);
    if (KT > 1) {
        uint32_t s1 = sb + STAGE_BYTES;
        load_stage_h(Arow + 64, Brow + 64, K, s1, s1 + BM * 128, tid);
    }

    int stage = 0;
    for (int kt = 0; kt < KT; kt++) {
        if (kt + 1 < KT) asm volatile("cp.async.wait_group 1;" ::: "memory");
        else             asm volatile("cp.async.wait_group 0;" ::: "memory");
        __syncthreads();   // stage kt ready + all warps done with stage being reloaded

        if (kt + 2 < KT) {
            int ls = (stage + 2) % NSTAGE;
            uint32_t Ab2 = sb + ls * STAGE_BYTES;
            load_stage_h(Arow + (kt + 2) * 64, Brow + (kt + 2) * 64, K,
                         Ab2, Ab2 + BM * 128, tid);
        }

        const uint32_t Ab = sb + stage * STAGE_BYTES;
        const uint32_t Bb = Ab + BM * 128;

#pragma unroll
        for (int kk = 0; kk < 4; kk++) {
            uint32_t af[4][4];
#pragma unroll
            for (int i = 0; i < 4; i++) {
                int m = m0 + i * 16 + rrA;
                uint32_t adr = Ab + m * 128 + (((kk * 2 + selA) ^ (m & 7)) << 4);
                asm volatile("ldmatrix.sync.aligned.m8n8.x4.shared.b16 {%0,%1,%2,%3}, [%4];"
                    : "=r"(af[i][0]), "=r"(af[i][1]), "=r"(af[i][2]), "=r"(af[i][3])
                    : "r"(adr));
            }
            uint32_t bf[4][2];
#pragma unroll
            for (int j = 0; j < 4; j++) {
                int n = n0 + j * 8 + rnB;
                uint32_t adr = Bb + n * 128 + (((kk * 2 + selB) ^ (n & 7)) << 4);
                asm volatile("ldmatrix.sync.aligned.m8n8.x2.shared.b16 {%0,%1}, [%2];"
                    : "=r"(bf[j][0]), "=r"(bf[j][1])
                    : "r"(adr));
            }
#pragma unroll
            for (int i = 0; i < 4; i++)
#pragma unroll
                for (int j = 0; j < 4; j++)
                    mma_f16(acc[i][j], af[i], bf[j]);
        }
        stage = (stage + 1) % NSTAGE;
    }

    // ---- epilogue ----
#pragma unroll
    for (int j = 0; j < 4; j++) {
        int col = col0 + n0 + j * 8 + tig * 2;
        float cb0 = 0.0f, cb1 = 0.0f;
        if (bias && !rowbias) { cb0 = bias[col]; cb1 = bias[col + 1]; }
#pragma unroll
        for (int i = 0; i < 4; i++) {
            int r = row0 + m0 + i * 16 + grp;
            float rb0 = 0.0f, rb8 = 0.0f;
            if (bias && rowbias) { rb0 = bias[r]; rb8 = bias[r + 8]; }
            float f0 = alpha * acc[i][j][0] + cb0 + rb0;
            float f1 = alpha * acc[i][j][1] + cb1 + rb0;
            float f2 = alpha * acc[i][j][2] + cb0 + rb8;
            float f3 = alpha * acc[i][j][3] + cb1 + rb8;
            store2(C, (size_t)r * N + col, f0, f1);
            store2(C, (size_t)(r + 8) * N + col, f2, f3);
        }
    }
}

// standalone GEMM kernel
template <typename OutT>
__global__ void __launch_bounds__(256, 2)
hgemm(const __half* __restrict__ A, const __half* __restrict__ Bt,
      const float* __restrict__ bias, OutT* __restrict__ C,
      int M, int N, int K, float alpha)
{
    extern __shared__ char smraw[];
    uint32_t sb = (smem_u32(smraw) + 127u) & ~127u;
    hgemm_core<OutT>(A, Bt, bias, C, M, N, K, alpha, false,
                     blockIdx.x, blockIdx.y, sb, threadIdx.x);
}

// fused QKV: z=0 -> q = xh@Wq^T'+bq, z=1 -> k, z=2 -> vT = Wv^T @ x^T (row bias)
__global__ void __launch_bounds__(256, 2)
qkv_fused(const __half* __restrict__ xh,
          const __half* __restrict__ wqT, const __half* __restrict__ wkT,
          const __half* __restrict__ wvT,
          const float* __restrict__ bq, const float* __restrict__ bk,
          const float* __restrict__ bv,
          __half* __restrict__ q, __half* __restrict__ k, __half* __restrict__ vT)
{
    extern __shared__ char smraw[];
    uint32_t sb = (smem_u32(smraw) + 127u) & ~127u;
    const int z = blockIdx.z;
    if (z < 2) {
        hgemm_core<__half>(xh, z ? wkT : wqT, z ? bk : bq, z ? k : q,
                           NTOK, DIM, DIM, 1.0f, false,
                           blockIdx.x, blockIdx.y, sb, threadIdx.x);
    } else {
        // vT[h][n]: A = wvT [DIM x DIM], Bt = xh [NTOK x DIM], bias per-row (h)
        hgemm_core<__half>(wvT, xh, bv, vT,
                           DIM, NTOK, DIM, 1.0f, true,
                           blockIdx.y, blockIdx.x, sb, threadIdx.x);
    }
}

// ------------------------- conversion / transpose kernels -------------------------
__global__ void __launch_bounds__(256)
f2h(const float* __restrict__ src, __half* __restrict__ dst, int n4)
{
    int i = blockIdx.x * blockDim.x + threadIdx.x;
    if (i < n4) {
        float4 v = reinterpret_cast<const float4*>(src)[i];
        __half2* d2 = reinterpret_cast<__half2*>(dst) + (size_t)i * 2;
        d2[0] = __floats2half2_rn(v.x, v.y);
        d2[1] = __floats2half2_rn(v.z, v.w);
    }
}

// 4 weight transposes in one launch (z selects pair), all DIM x DIM
__global__ void __launch_bounds__(256)
transpose_w4(const float* __restrict__ s0, __half* __restrict__ d0,
             const float* __restrict__ s1, __half* __restrict__ d1,
             const float* __restrict__ s2, __half* __restrict__ d2,
             const float* __restrict__ s3, __half* __restrict__ d3)
{
    const float* src; __half* dst;
    switch (blockIdx.z) {
        case 0: src = s0; dst = d0; break;
        case 1: src = s1; dst = d1; break;
        case 2: src = s2; dst = d2; break;
        default: src = s3; dst = d3; break;
    }
    __shared__ float t[32][33];
    int c = blockIdx.x * 32 + threadIdx.x;
    int r = blockIdx.y * 32 + threadIdx.y;
#pragma unroll
    for (int i = 0; i < 32; i += 8)
        t[threadIdx.y + i][threadIdx.x] = src[(size_t)(r + i) * DIM + c];
    __syncthreads();
    int c2 = blockIdx.y * 32 + threadIdx.x;
    int r2 = blockIdx.x * 32 + threadIdx.y;
#pragma unroll
    for (int i = 0; i < 32; i += 8)
        dst[(size_t)(r2 + i) * DIM + c2] = __float2half_rn(t[threadIdx.x][threadIdx.y + i]);
}

// ------------------------- row softmax (half in/out, fp32 math) -------------------------
__global__ void __launch_bounds__(256)
softmax_h(__half* __restrict__ S, int n)
{
    const int row = blockIdx.x;
    const int tid = threadIdx.x;
    __half2* rp = reinterpret_cast<__half2*>(S + (size_t)row * n);

    float2 v[16];
#pragma unroll
    for (int i = 0; i < 16; i++) v[i] = __half22float2(rp[tid + i * 256]);

    float m = -INFINITY;
#pragma unroll
    for (int i = 0; i < 16; i++) m = fmaxf(m, fmaxf(v[i].x, v[i].y));
#pragma unroll
    for (int o = 16; o > 0; o >>= 1) m = fmaxf(m, __shfl_xor_sync(0xFFFFFFFFu, m, o));
    __shared__ float red[8];
    if ((tid & 31) == 0) red[tid >> 5] = m;
    __syncthreads();
    if (tid < 32) {
        float t = (tid < 8) ? red[tid] : -INFINITY;
#pragma unroll
        for (int o = 4; o > 0; o >>= 1) t = fmaxf(t, __shfl_xor_sync(0xFFFFFFFFu, t, o));
        if (tid == 0) red[0] = t;
    }
    __syncthreads();
    m = red[0];

    float s = 0.0f;
#pragma unroll
    for (int i = 0; i < 16; i++) {
        v[i].x = __expf(v[i].x - m);
        v[i].y = __expf(v[i].y - m);
        s += v[i].x + v[i].y;
    }
#pragma unroll
    for (int o = 16; o > 0; o >>= 1) s += __shfl_xor_sync(0xFFFFFFFFu, s, o);
    __syncthreads();
    if ((tid & 31) == 0) red[tid >> 5] = s;
    __syncthreads();
    if (tid < 32) {
        float t = (tid < 8) ? red[tid] : 0.0f;
#pragma unroll
        for (int o = 4; o > 0; o >>= 1) t += __shfl_xor_sync(0xFFFFFFFFu, t, o);
        if (tid == 0) red[0] = t;
    }
    __syncthreads();
    const float inv = 1.0f / red[0];

#pragma unroll
    for (int i = 0; i < 16; i++)
        rp[tid + i * 256] = __floats2half2_rn(v[i].x * inv, v[i].y * inv);
}

// ------------------------- launch -------------------------
extern "C" void kernel_launch(void* const* d_in, const int* in_sizes, int n_in,
                              void* d_out, int out_size)
{
    const float* x  = (const float*)d_in[0];
    const float* Wq = (const float*)d_in[1];
    const float* bq = (const float*)d_in[2];
    const float* Wk = (const float*)d_in[3];
    const float* bk = (const float*)d_in[4];
    const float* Wv = (const float*)d_in[5];
    const float* bv = (const float*)d_in[6];
    const float* Wo = (const float*)d_in[7];
    const float* bo = (const float*)d_in[8];
    float* out = (float*)d_out;

    __half *xh, *wqT, *wkT, *wvT, *woT, *q, *k, *vT, *t, *s;
    cudaGetSymbolAddress((void**)&xh,  g_xh);
    cudaGetSymbolAddress((void**)&wqT, g_wqT);
    cudaGetSymbolAddress((void**)&wkT, g_wkT);
    cudaGetSymbolAddress((void**)&wvT, g_wvT);
    cudaGetSymbolAddress((void**)&woT, g_woT);
    cudaGetSymbolAddress((void**)&q,   g_q);
    cudaGetSymbolAddress((void**)&k,   g_k);
    cudaGetSymbolAddress((void**)&vT,  g_vT);
    cudaGetSymbolAddress((void**)&t,   g_t);
    cudaGetSymbolAddress((void**)&s,   g_s);

    cudaFuncSetAttribute(hgemm<__half>, cudaFuncAttributeMaxDynamicSharedMemorySize, SMEM_BYTES);
    cudaFuncSetAttribute(hgemm<float>,  cudaFuncAttributeMaxDynamicSharedMemorySize, SMEM_BYTES);
    cudaFuncSetAttribute(qkv_fused,     cudaFuncAttributeMaxDynamicSharedMemorySize, SMEM_BYTES);

    const float scale = 1.0f / sqrtf((float)DIM);
    dim3 blk(256);

    // inputs -> half; weights -> transposed half [N][K] (one launch for all 4)
    f2h<<<(NTOK * DIM / 4 + 255) / 256, blk>>>(x, xh, NTOK * DIM / 4);
    {
        dim3 tb(32, 8), tg(DIM / 32, DIM / 32, 4);
        transpose_w4<<<tg, tb>>>(Wq, wqT, Wk, wkT, Wv, wvT, Wo, woT);
    }

    // fused q, k, vT (vT computed directly transposed; no separate transpose pass)
    {
        dim3 g(DIM / 128, NTOK / 128, 3);   // (4, 64, 3)
        qkv_fused<<<g, blk, SMEM_BYTES>>>(xh, wqT, wkT, wvT, bq, bk, bv, q, k, vT);
    }

    // scores = scale * q @ k^T  (half out, 128 MB)
    {
        dim3 g(NTOK / 128, NTOK / 128);     // (64, 64)
        hgemm<__half><<<g, blk, SMEM_BYTES>>>(q, k, nullptr, s, NTOK, NTOK, DIM, scale);
    }

    // softmax rows in place
    softmax_h<<<NTOK, blk>>>(s, NTOK);

    // attended = attn @ v  (= attn @ vT^T)
    {
        dim3 g(DIM / 128, NTOK / 128);      // (4, 64)
        hgemm<__half><<<g, blk, SMEM_BYTES>>>(s, vT, nullptr, t, NTOK, DIM, NTOK, 1.0f);
    }

    // out = attended @ Wo + bo  (float out)
    {
        dim3 g(DIM / 128, NTOK / 128);
        hgemm<float><<<g, blk, SMEM_BYTES>>>(t, woT, bo, out, NTOK, DIM, DIM, 1.0f);
    }
}